// round 2
// baseline (speedup 1.0000x reference)
#include <cuda_runtime.h>

// Correlation (cost volume), max_disp=4:
//   out[b, dx*9+dy, h, w] = (1/128) * sum_c x1[b,c,h,w] * x2[b,c,h+dx-4, w+dy-4]
// with zero padding outside x2's spatial extent.
//
// Shapes: x1,x2 [8,128,128,128] f32 ; out [8,81,128,128] f32.

#define CC_C   128
#define CC_H   128
#define CC_W   128
#define CC_B   8
#define CC_D   4
#define CC_ND  9          // 2*D+1
#define CC_NOFF 81
#define CC_TH  2          // output rows per block
#define CC_PX  8          // pixels per thread along w
#define CC_NWG (CC_W / CC_PX)       // 16
#define CC_CCH 4          // channels per smem chunk
#define CC_NCHUNK (CC_C / CC_CCH)   // 32
#define CC_X2ROWS (CC_TH + 2*CC_D)  // 10
#define CC_X2W  (CC_W + 2*CC_D)     // 136 floats per padded row
#define CC_NTHREADS (CC_ND * CC_TH * CC_NWG)  // 288

__global__ __launch_bounds__(CC_NTHREADS)
void corr_kernel(const float* __restrict__ x1,
                 const float* __restrict__ x2,
                 float* __restrict__ out)
{
    __shared__ __align__(16) float x1s[CC_CCH][CC_TH][CC_W];
    __shared__ __align__(16) float x2s[CC_CCH][CC_X2ROWS][CC_X2W];

    const int tid  = threadIdx.x;
    const int dx   = tid >> 5;        // warp id = dx in [0,9)
    const int lane = tid & 31;
    const int hl   = lane >> 4;       // 0..1 : local output row
    const int wg   = lane & 15;       // 0..15 : 8-pixel group along w

    const int b  = blockIdx.y;
    const int h0 = blockIdx.x * CC_TH;

    float acc[CC_ND][CC_PX];
#pragma unroll
    for (int dy = 0; dy < CC_ND; ++dy)
#pragma unroll
        for (int p = 0; p < CC_PX; ++p)
            acc[dy][p] = 0.0f;

    for (int chunk = 0; chunk < CC_NCHUNK; ++chunk) {
        const int cb = chunk * CC_CCH;
        __syncthreads();

        // ---- fill x1 tile: CC_CCH*CC_TH*(W/4) = 256 float4 ----
        for (int i = tid; i < CC_CCH * CC_TH * (CC_W / 4); i += CC_NTHREADS) {
            const int c   = i >> 6;        // / (TH*W/4 = 64)
            const int rem = i & 63;
            const int hh  = rem >> 5;      // / 32
            const int q   = rem & 31;
            const float4 g = *(const float4*)
                &x1[(((size_t)(b * CC_C + cb + c) * CC_H) + h0 + hh) * CC_W + 4 * q];
            *(float4*)&x1s[c][hh][4 * q] = g;
        }

        // ---- zero the left/right 4-float pads of every x2 row ----
        for (int i = tid; i < CC_CCH * CC_X2ROWS * 2; i += CC_NTHREADS) {
            const int c    = i / (CC_X2ROWS * 2);
            const int rem  = i - c * (CC_X2ROWS * 2);
            const int r    = rem >> 1;
            const int side = rem & 1;
            *(float4*)&x2s[c][r][side ? (CC_W + CC_D) : 0] = make_float4(0.f, 0.f, 0.f, 0.f);
        }

        // ---- fill x2 tile body: CC_CCH*10*(W/4) = 1280 float4 ----
        for (int i = tid; i < CC_CCH * CC_X2ROWS * (CC_W / 4); i += CC_NTHREADS) {
            const int c    = i / (CC_X2ROWS * (CC_W / 4));   // / 320
            const int rem  = i - c * (CC_X2ROWS * (CC_W / 4));
            const int r    = rem >> 5;
            const int q    = rem & 31;
            const int grow = h0 - CC_D + r;
            float4 g = make_float4(0.f, 0.f, 0.f, 0.f);
            if (grow >= 0 && grow < CC_H)
                g = *(const float4*)
                    &x2[(((size_t)(b * CC_C + cb + c) * CC_H) + grow) * CC_W + 4 * q];
            *(float4*)&x2s[c][r][CC_D + 4 * q] = g;
        }
        __syncthreads();

        // ---- compute: per channel, 6 LDS.128 -> 72 FFMA per thread ----
#pragma unroll
        for (int c = 0; c < CC_CCH; ++c) {
            float a[CC_PX];
            {
                const float4 a0 = *(const float4*)&x1s[c][hl][CC_PX * wg];
                const float4 a1 = *(const float4*)&x1s[c][hl][CC_PX * wg + 4];
                a[0] = a0.x; a[1] = a0.y; a[2] = a0.z; a[3] = a0.w;
                a[4] = a1.x; a[5] = a1.y; a[6] = a1.z; a[7] = a1.w;
            }
            float v[CC_PX + 2 * CC_D];  // 16-wide x2 window
            {
                const float* vp = &x2s[c][hl + dx][CC_PX * wg];  // pad offset already folded in
                const float4 V0 = ((const float4*)vp)[0];
                const float4 V1 = ((const float4*)vp)[1];
                const float4 V2 = ((const float4*)vp)[2];
                const float4 V3 = ((const float4*)vp)[3];
                v[0]  = V0.x; v[1]  = V0.y; v[2]  = V0.z; v[3]  = V0.w;
                v[4]  = V1.x; v[5]  = V1.y; v[6]  = V1.z; v[7]  = V1.w;
                v[8]  = V2.x; v[9]  = V2.y; v[10] = V2.z; v[11] = V2.w;
                v[12] = V3.x; v[13] = V3.y; v[14] = V3.z; v[15] = V3.w;
            }
#pragma unroll
            for (int dy = 0; dy < CC_ND; ++dy)
#pragma unroll
                for (int p = 0; p < CC_PX; ++p)
                    acc[dy][p] = fmaf(a[p], v[p + dy], acc[dy][p]);
        }
    }

    // ---- epilogue: scale by 1/C and store 9 x 8 contiguous floats ----
    const float inv = 1.0f / (float)CC_C;
    const int hh = h0 + hl;
#pragma unroll
    for (int dy = 0; dy < CC_ND; ++dy) {
        const int o = dx * CC_ND + dy;
        float4 r0, r1;
        r0.x = acc[dy][0] * inv; r0.y = acc[dy][1] * inv;
        r0.z = acc[dy][2] * inv; r0.w = acc[dy][3] * inv;
        r1.x = acc[dy][4] * inv; r1.y = acc[dy][5] * inv;
        r1.z = acc[dy][6] * inv; r1.w = acc[dy][7] * inv;
        float* op = &out[(((size_t)(b * CC_NOFF + o) * CC_H) + hh) * CC_W + CC_PX * wg];
        ((float4*)op)[0] = r0;
        ((float4*)op)[1] = r1;
    }
}

extern "C" void kernel_launch(void* const* d_in, const int* in_sizes, int n_in,
                              void* d_out, int out_size)
{
    const float* x1 = (const float*)d_in[0];
    const float* x2 = (const float*)d_in[1];
    float* out = (float*)d_out;

    dim3 grid(CC_H / CC_TH, CC_B);   // (64, 8) = 512 blocks
    corr_kernel<<<grid, CC_NTHREADS>>>(x1, x2, out);
}

// round 3
// speedup vs baseline: 3.0615x; 3.0615x over previous
#include <cuda_runtime.h>

// Correlation cost volume, max_disp=4.
// out[b, dx*9+dy, h, w] = (1/128) * sum_c x1[b,c,h,w] * x2pad[b,c,h+dx,w+dy]
// x1,x2: [8,128,128,128] f32 ; out: [8,81,128,128] f32.

#define CC_C   128
#define CC_H   128
#define CC_W   128
#define CC_B   8
#define CC_D   4
#define CC_ND  9
#define CC_NOFF 81
#define CC_TH  2                      // output rows per block
#define CC_CCH 4                      // channels per pipeline chunk
#define CC_NCHUNK (CC_C / CC_CCH)     // 32
#define CC_X2R (CC_TH + 2*CC_D)       // 10 padded x2 rows
#define CC_X2W (CC_W + 2*CC_D)        // 136 floats per padded row
#define NSTAGE 3
#define NTH    576                    // 18 warps: warp = dxi + 9*hl; lane = w-group (4 px)

#define X1SF (CC_CCH*CC_TH*CC_W)      // 1024 floats / stage
#define X2SF (CC_CCH*CC_X2R*CC_X2W)   // 5440 floats / stage
#define STF  (X1SF + X2SF)            // 6464 floats / stage (25856 B, 16B-aligned)
#define SMEM_BYTES (NSTAGE * STF * 4) // 77568 B

#define N_X1F4 (X1SF / 4)                      // 256 float4 fills
#define N_X2F4 (CC_CCH * CC_X2R * (CC_W/4))    // 1280 float4 fills (body)
#define N_FILL (N_X1F4 + N_X2F4)               // 1536

// ---- packed f32x2 helpers ----
#define FMA2(acc, a, b) \
    asm("fma.rn.f32x2 %0, %1, %2, %0;" : "+l"(acc) : "l"(a), "l"(b))
#define PACK2(d, lo, hi) \
    asm("mov.b64 %0, {%1, %2};" : "=l"(d) : "f"(lo), "f"(hi))
#define UNPACK2(lo, hi, v) \
    asm("mov.b64 {%0, %1}, %2;" : "=f"(lo), "=f"(hi) : "l"(v))

__device__ __forceinline__ void cp16(unsigned dst, const void* src, int src_bytes) {
    asm volatile("cp.async.cg.shared.global [%0], [%1], 16, %2;\n"
                 :: "r"(dst), "l"(src), "r"(src_bytes));
}

extern "C" __global__ void __launch_bounds__(NTH, 1)
corr_kernel(const float* __restrict__ x1,
            const float* __restrict__ x2,
            float* __restrict__ out)
{
    extern __shared__ float smem[];
    const int tid  = threadIdx.x;
    const int warp = tid >> 5;
    const int lane = tid & 31;
    const int dxi  = warp % CC_ND;    // 0..8
    const int hl   = warp / CC_ND;    // 0..1
    const int b    = blockIdx.y;
    const int h0   = blockIdx.x * CC_TH;

    unsigned smem_u32;
    asm("{ .reg .u64 t; cvta.to.shared.u64 t, %1; cvt.u32.u64 %0, t; }"
        : "=r"(smem_u32) : "l"(smem));

    // ---- zero left/right pads once, for every stage (never overwritten) ----
    for (int i = tid; i < NSTAGE * CC_CCH * CC_X2R * 2; i += NTH) {
        const int s    = i / (CC_CCH * CC_X2R * 2);
        const int rem  = i % (CC_CCH * CC_X2R * 2);
        const int cr   = rem >> 1;          // c*X2R + r
        const int side = rem & 1;
        float* p = smem + s * STF + X1SF + cr * CC_X2W + (side ? (CC_D + CC_W) : 0);
        *(float4*)p = make_float4(0.f, 0.f, 0.f, 0.f);
    }

    // ---- precompute fill items (<=3 cp.async per thread per chunk) ----
    int        it_valid[3];
    unsigned   it_dst[3];
    const float* it_src[3];
    int        it_pred[3];
#pragma unroll
    for (int k = 0; k < 3; ++k) {
        const int i = tid + k * NTH;
        it_valid[k] = (i < N_FILL);
        if (i < N_X1F4) {
            const int c = i >> 6, rem = i & 63, hh = rem >> 5, q = rem & 31;
            it_dst[k]  = smem_u32 + (unsigned)(c * CC_TH * CC_W + hh * CC_W + 4 * q) * 4u;
            it_src[k]  = x1 + ((size_t)(b * CC_C + c) * CC_H + (h0 + hh)) * CC_W + 4 * q;
            it_pred[k] = 16;
        } else if (i < N_FILL) {
            const int j   = i - N_X1F4;
            const int c   = j / (CC_X2R * (CC_W / 4));
            const int rem = j % (CC_X2R * (CC_W / 4));
            const int r   = rem >> 5, q = rem & 31;
            const int grow = h0 - CC_D + r;
            const int ok   = (grow >= 0 && grow < CC_H);
            it_dst[k]  = smem_u32 +
                (unsigned)(X1SF + c * CC_X2R * CC_X2W + r * CC_X2W + CC_D + 4 * q) * 4u;
            it_src[k]  = x2 + ((size_t)(b * CC_C + c) * CC_H + (ok ? grow : 0)) * CC_W + 4 * q;
            it_pred[k] = ok ? 16 : 0;   // src_bytes=0 -> zero-fill 16B
        } else {
            it_dst[k] = smem_u32; it_src[k] = x1; it_pred[k] = 0;
        }
    }

    // ---- pipeline prologue: fill chunks 0,1 ----
#pragma unroll
    for (int pc = 0; pc < NSTAGE - 1; ++pc) {
        const unsigned stoff = (unsigned)(pc % NSTAGE) * (STF * 4u);
        const size_t   coff  = (size_t)pc * CC_CCH * CC_H * CC_W;
#pragma unroll
        for (int k = 0; k < 3; ++k)
            if (it_valid[k]) cp16(it_dst[k] + stoff, it_src[k] + coff, it_pred[k]);
        asm volatile("cp.async.commit_group;");
    }

    unsigned long long acc2[CC_ND][2] = {};   // 9 dy x 2 pixel-pairs, packed f32x2

    for (int chunk = 0; chunk < CC_NCHUNK; ++chunk) {
        asm volatile("cp.async.wait_group 1;");
        __syncthreads();   // stage data visible; all warps done with stage being refilled

        {   // issue fill for chunk+2 into stage (chunk+2)%3
            const int fc = chunk + NSTAGE - 1;
            if (fc < CC_NCHUNK) {
                const unsigned stoff = (unsigned)(fc % NSTAGE) * (STF * 4u);
                const size_t   coff  = (size_t)fc * CC_CCH * CC_H * CC_W;
#pragma unroll
                for (int k = 0; k < 3; ++k)
                    if (it_valid[k]) cp16(it_dst[k] + stoff, it_src[k] + coff, it_pred[k]);
            }
            asm volatile("cp.async.commit_group;");
        }

        const int st = chunk % NSTAGE;
        const float* x1p = smem + st * STF + hl * CC_W + 4 * lane;
        const float* x2p = smem + st * STF + X1SF + (hl + dxi) * CC_X2W + 4 * lane;

#pragma unroll
        for (int c = 0; c < CC_CCH; ++c) {
            const float4 A  = *(const float4*)(x1p + c * CC_TH * CC_W);
            const float4 V0 = *(const float4*)(x2p + c * CC_X2R * CC_X2W);
            const float4 V1 = *(const float4*)(x2p + c * CC_X2R * CC_X2W + 4);
            const float4 V2 = *(const float4*)(x2p + c * CC_X2R * CC_X2W + 8);

            unsigned long long ap0, ap1, e0, e1, e2, e3, e4, e5, o0, o1, o2, o3, o4;
            PACK2(ap0, A.x, A.y);  PACK2(ap1, A.z, A.w);
            PACK2(e0, V0.x, V0.y); PACK2(e1, V0.z, V0.w);
            PACK2(e2, V1.x, V1.y); PACK2(e3, V1.z, V1.w);
            PACK2(e4, V2.x, V2.y); PACK2(e5, V2.z, V2.w);
            PACK2(o0, V0.y, V0.z); PACK2(o1, V0.w, V1.x);
            PACK2(o2, V1.y, V1.z); PACK2(o3, V1.w, V2.x);
            PACK2(o4, V2.y, V2.z);

            // even dy: pair index e[dy/2 + j]
            FMA2(acc2[0][0], ap0, e0); FMA2(acc2[0][1], ap1, e1);
            FMA2(acc2[2][0], ap0, e1); FMA2(acc2[2][1], ap1, e2);
            FMA2(acc2[4][0], ap0, e2); FMA2(acc2[4][1], ap1, e3);
            FMA2(acc2[6][0], ap0, e3); FMA2(acc2[6][1], ap1, e4);
            FMA2(acc2[8][0], ap0, e4); FMA2(acc2[8][1], ap1, e5);
            // odd dy: pair index o[(dy-1)/2 + j]
            FMA2(acc2[1][0], ap0, o0); FMA2(acc2[1][1], ap1, o1);
            FMA2(acc2[3][0], ap0, o1); FMA2(acc2[3][1], ap1, o2);
            FMA2(acc2[5][0], ap0, o2); FMA2(acc2[5][1], ap1, o3);
            FMA2(acc2[7][0], ap0, o3); FMA2(acc2[7][1], ap1, o4);
        }
    }

    // ---- epilogue: scale by 1/C, store 9 float4 per thread ----
    const float inv = 1.0f / (float)CC_C;
    const int h = h0 + hl;
#pragma unroll
    for (int dy = 0; dy < CC_ND; ++dy) {
        float f0, f1, f2, f3;
        UNPACK2(f0, f1, acc2[dy][0]);
        UNPACK2(f2, f3, acc2[dy][1]);
        float4 r;
        r.x = f0 * inv; r.y = f1 * inv; r.z = f2 * inv; r.w = f3 * inv;
        *(float4*)&out[(((size_t)(b * CC_NOFF + dxi * CC_ND + dy) * CC_H) + h) * CC_W + 4 * lane] = r;
    }
}

extern "C" void kernel_launch(void* const* d_in, const int* in_sizes, int n_in,
                              void* d_out, int out_size)
{
    const float* x1 = (const float*)d_in[0];
    const float* x2 = (const float*)d_in[1];
    float* out = (float*)d_out;

    cudaFuncSetAttribute(corr_kernel,
                         cudaFuncAttributeMaxDynamicSharedMemorySize, SMEM_BYTES);
    dim3 grid(CC_H / CC_TH, CC_B);   // (64, 8) = 512 blocks
    corr_kernel<<<grid, NTH, SMEM_BYTES>>>(x1, x2, out);
}

// round 4
// speedup vs baseline: 3.3291x; 1.0874x over previous
#include <cuda_runtime.h>

// Correlation cost volume, max_disp=4.
// out[b, dx*9+dy, h, w] = (1/128) * sum_c x1[b,c,h,w] * x2pad[b,c,h+dx,w+dy]
// x1,x2: [8,128,128,128] f32 ; out: [8,81,128,128] f32.

#define CC_C   128
#define CC_H   128
#define CC_W   128
#define CC_B   8
#define CC_D   4
#define CC_ND  9
#define CC_NOFF 81
#define CC_TH  2                      // output rows per block
#define CC_CCH 8                      // channels per pipeline chunk
#define CC_NCHUNK (CC_C / CC_CCH)     // 16
#define CC_X2R (CC_TH + 2*CC_D)       // 10 padded x2 rows
#define CC_X2W (CC_W + 2*CC_D)        // 136 floats per padded row
#define NSTAGE 3
#define NTH    576                    // 18 warps: warp = dxi + 9*hl; lane = 4px w-group

#define X1SF (CC_CCH*CC_TH*CC_W)      // 2048 floats / stage
#define X2SF (CC_CCH*CC_X2R*CC_X2W)   // 10880 floats / stage
#define STF  (X1SF + X2SF)            // 12928 floats / stage (51712 B)
#define SMEM_BYTES (NSTAGE * STF * 4) // 155136 B

#define N_X1F4 (X1SF / 4)                      // 512 float4 fills
#define N_X2F4 (CC_CCH * CC_X2R * (CC_W/4))    // 2560 float4 fills (body)
#define N_FILL (N_X1F4 + N_X2F4)               // 3072
#define N_IT   6                               // fills per thread per chunk
#define CHUNK_SRC_BYTES (CC_CCH * CC_H * CC_W * 4)   // 524288

typedef unsigned long long u64t;

union F4U { float4 f; u64t u[2]; float s[4]; };

#define FMA2(acc, a, b) \
    asm("fma.rn.f32x2 %0, %1, %2, %0;" : "+l"(acc) : "l"(a), "l"(b))
#define PACK2(d, lo, hi) \
    asm("mov.b64 %0, {%1, %2};" : "=l"(d) : "f"(lo), "f"(hi))
#define UNPACK2(lo, hi, v) \
    asm("mov.b64 {%0, %1}, %2;" : "=f"(lo), "=f"(hi) : "l"(v))

__device__ __forceinline__ void cp16(unsigned dst, const void* src, int src_bytes) {
    asm volatile("cp.async.cg.shared.global [%0], [%1], 16, %2;\n"
                 :: "r"(dst), "l"(src), "r"(src_bytes));
}

extern "C" __global__ void __launch_bounds__(NTH, 1)
corr_kernel(const float* __restrict__ x1,
            const float* __restrict__ x2,
            float* __restrict__ out)
{
    extern __shared__ float smem[];
    const int tid  = threadIdx.x;
    const int warp = tid >> 5;
    const int lane = tid & 31;
    const int dxi  = warp % CC_ND;    // 0..8
    const int hl   = warp / CC_ND;    // 0..1
    const int b    = blockIdx.y;
    const int h0   = blockIdx.x * CC_TH;

    unsigned smem_u32;
    asm("{ .reg .u64 t; cvta.to.shared.u64 t, %1; cvt.u32.u64 %0, t; }"
        : "=r"(smem_u32) : "l"(smem));

    // ---- zero left/right x2 pads once per stage (never overwritten) ----
    for (int i = tid; i < NSTAGE * CC_CCH * CC_X2R * 2; i += NTH) {
        const int s    = i / (CC_CCH * CC_X2R * 2);
        const int rem  = i % (CC_CCH * CC_X2R * 2);
        const int cr   = rem >> 1;
        const int side = rem & 1;
        float* p = smem + s * STF + X1SF + cr * CC_X2W + (side ? (CC_D + CC_W) : 0);
        *(float4*)p = make_float4(0.f, 0.f, 0.f, 0.f);
    }

    // ---- precompute fill items: N_IT cp.async per thread per chunk ----
    const float* bx1 = x1 + (size_t)b * CC_C * CC_H * CC_W;
    const float* bx2 = x2 + (size_t)b * CC_C * CC_H * CC_W;
    unsigned  it_dst[N_IT];        // smem byte address (stage 0)
    unsigned  it_src[N_IT];        // byte offset from batch base
    unsigned  predmask = 0;        // bit k: 16-byte copy, else zero-fill
    unsigned  validmask = 0;       // bit k: item exists
#pragma unroll
    for (int k = 0; k < N_IT; ++k) {
        const int i = tid + k * NTH;
        if (i >= N_FILL) { it_dst[k] = smem_u32; it_src[k] = 0; continue; }
        validmask |= 1u << k;
        if (i < N_X1F4) {
            const int c = i >> 6, rem = i & 63, hh = rem >> 5, q = rem & 31;
            it_dst[k] = smem_u32 + (unsigned)(c * CC_TH * CC_W + hh * CC_W + 4 * q) * 4u;
            it_src[k] = (unsigned)(((c * CC_H) + h0 + hh) * CC_W + 4 * q) * 4u;
            predmask |= 1u << k;
        } else {
            const int j   = i - N_X1F4;
            const int c   = j / (CC_X2R * (CC_W / 4));
            const int rem = j % (CC_X2R * (CC_W / 4));
            const int r   = rem >> 5, q = rem & 31;
            const int grow = h0 - CC_D + r;
            const int ok   = (grow >= 0 && grow < CC_H);
            it_dst[k] = smem_u32 +
                (unsigned)(X1SF + (c * CC_X2R + r) * CC_X2W + CC_D + 4 * q) * 4u;
            it_src[k] = (unsigned)(((c * CC_H) + (ok ? grow : 0)) * CC_W + 4 * q) * 4u;
            if (ok) predmask |= 1u << k;
        }
    }

    // ---- pipeline prologue: fill chunks 0,1 ----
#pragma unroll
    for (int pc = 0; pc < NSTAGE - 1; ++pc) {
        const unsigned stoff = (unsigned)pc * (STF * 4u);
        const unsigned coff  = (unsigned)pc * CHUNK_SRC_BYTES;
#pragma unroll
        for (int k = 0; k < N_IT; ++k)
            if (validmask & (1u << k)) {
                const float* base = (k == 0 && tid < N_X1F4) ? bx1 : bx2;
                cp16(it_dst[k] + stoff, (const char*)base + it_src[k] + coff,
                     (predmask >> k & 1) ? 16 : 0);
            }
        asm volatile("cp.async.commit_group;");
    }

    u64t acc2[CC_ND][2] = {};   // 9 dy x 2 pixel-pairs (packed f32x2)

    for (int chunk = 0; chunk < CC_NCHUNK; ++chunk) {
        asm volatile("cp.async.wait_group 1;");
        __syncthreads();

        {   // fill chunk+2 into stage (chunk+2)%3
            const int fc = chunk + NSTAGE - 1;
            if (fc < CC_NCHUNK) {
                const unsigned stoff = (unsigned)(fc % NSTAGE) * (STF * 4u);
                const unsigned coff  = (unsigned)fc * CHUNK_SRC_BYTES;
#pragma unroll
                for (int k = 0; k < N_IT; ++k)
                    if (validmask & (1u << k)) {
                        const float* base = (k == 0 && tid < N_X1F4) ? bx1 : bx2;
                        cp16(it_dst[k] + stoff, (const char*)base + it_src[k] + coff,
                             (predmask >> k & 1) ? 16 : 0);
                    }
            }
            asm volatile("cp.async.commit_group;");
        }

        const int st = chunk % NSTAGE;
        const float* x1p = smem + st * STF + hl * CC_W + 4 * lane;
        const float* x2p = smem + st * STF + X1SF + (hl + dxi) * CC_X2W + 4 * lane;

#pragma unroll
        for (int c = 0; c < CC_CCH; ++c) {
            F4U A, V0, V1, V2;
            A.f  = *(const float4*)(x1p + c * CC_TH * CC_W);
            V0.f = *(const float4*)(x2p + c * CC_X2R * CC_X2W);
            V1.f = *(const float4*)(x2p + c * CC_X2R * CC_X2W + 4);
            V2.f = *(const float4*)(x2p + c * CC_X2R * CC_X2W + 8);

            // even pairs are free (aligned halves of the LDS.128 results)
            const u64t ap0 = A.u[0], ap1 = A.u[1];
            const u64t e0 = V0.u[0], e1 = V0.u[1];
            const u64t e2 = V1.u[0], e3 = V1.u[1];
            const u64t e4 = V2.u[0], e5 = V2.u[1];
            u64t o0, o1, o2, o3, o4;   // odd-parity pairs: 5 packs
            PACK2(o0, V0.s[1], V0.s[2]);
            PACK2(o1, V0.s[3], V1.s[0]);
            PACK2(o2, V1.s[1], V1.s[2]);
            PACK2(o3, V1.s[3], V2.s[0]);
            PACK2(o4, V2.s[1], V2.s[2]);

            FMA2(acc2[0][0], ap0, e0); FMA2(acc2[0][1], ap1, e1);
            FMA2(acc2[2][0], ap0, e1); FMA2(acc2[2][1], ap1, e2);
            FMA2(acc2[4][0], ap0, e2); FMA2(acc2[4][1], ap1, e3);
            FMA2(acc2[6][0], ap0, e3); FMA2(acc2[6][1], ap1, e4);
            FMA2(acc2[8][0], ap0, e4); FMA2(acc2[8][1], ap1, e5);
            FMA2(acc2[1][0], ap0, o0); FMA2(acc2[1][1], ap1, o1);
            FMA2(acc2[3][0], ap0, o1); FMA2(acc2[3][1], ap1, o2);
            FMA2(acc2[5][0], ap0, o2); FMA2(acc2[5][1], ap1, o3);
            FMA2(acc2[7][0], ap0, o3); FMA2(acc2[7][1], ap1, o4);
        }
    }

    // ---- epilogue ----
    const float inv = 1.0f / (float)CC_C;
    const int h = h0 + hl;
#pragma unroll
    for (int dy = 0; dy < CC_ND; ++dy) {
        float f0, f1, f2, f3;
        UNPACK2(f0, f1, acc2[dy][0]);
        UNPACK2(f2, f3, acc2[dy][1]);
        float4 r;
        r.x = f0 * inv; r.y = f1 * inv; r.z = f2 * inv; r.w = f3 * inv;
        *(float4*)&out[(((size_t)(b * CC_NOFF + dxi * CC_ND + dy) * CC_H) + h) * CC_W + 4 * lane] = r;
    }
}

extern "C" void kernel_launch(void* const* d_in, const int* in_sizes, int n_in,
                              void* d_out, int out_size)
{
    const float* x1 = (const float*)d_in[0];
    const float* x2 = (const float*)d_in[1];
    float* out = (float*)d_out;

    cudaFuncSetAttribute(corr_kernel,
                         cudaFuncAttributeMaxDynamicSharedMemorySize, SMEM_BYTES);
    dim3 grid(CC_H / CC_TH, CC_B);   // (64, 8) = 512 blocks
    corr_kernel<<<grid, NTH, SMEM_BYTES>>>(x1, x2, out);
}